// round 1
// baseline (speedup 1.0000x reference)
#include <cuda_runtime.h>
#include <math.h>

#define BB 2
#define TT 2048
#define DD 2048
#define HH 16
#define HD 128
#define ROWS (BB*TT)              // 4096
#define EPSV 1.1920929e-07f       // np.finfo(np.float32).eps

// ---------------- scratch (device globals: allocation-free) ----------------
__device__ float d_xqn [ROWS*DD];                 // rms(x)*g_q
__device__ float d_xkvn[ROWS*DD];                 // rms(x)*g_kv
__device__ float d_qlin[ROWS*DD];                 // x@Wq+bq
__device__ float d_kvlin[ROWS*2*DD];              // x@Wkv+bkv
__device__ float d_qn[BB*HH*TT*HD];               // [B,H,T,d] rms-head(q)
__device__ float d_kn[BB*HH*TT*HD];               // [B,H,T,d] rms-head(k)
__device__ float d_vt[BB*HH*TT*HD];               // [B,H,T,d] v
__device__ float d_sc[(size_t)BB*HH*TT*TT];       // [B,H,T,T] scores/probs (537MB)
__device__ float d_wv[BB*HH*TT*HD];               // [B,H,T,d] attn@v
__device__ float d_wvt[ROWS*DD];                  // [B*T, D]

// ---------------- reductions ----------------
__device__ __forceinline__ float blockReduceSum(float v, float* sh) {
    __syncthreads();                      // safe reuse of sh
    int lane = threadIdx.x & 31, w = threadIdx.x >> 5;
    #pragma unroll
    for (int o = 16; o > 0; o >>= 1) v += __shfl_down_sync(0xffffffffu, v, o);
    if (lane == 0) sh[w] = v;
    __syncthreads();
    int nw = blockDim.x >> 5;
    v = (threadIdx.x < nw) ? sh[threadIdx.x] : 0.0f;
    if (w == 0) {
        #pragma unroll
        for (int o = 16; o > 0; o >>= 1) v += __shfl_down_sync(0xffffffffu, v, o);
        if (lane == 0) sh[0] = v;
    }
    __syncthreads();
    return sh[0];
}

__device__ __forceinline__ float blockReduceMax(float v, float* sh) {
    __syncthreads();
    int lane = threadIdx.x & 31, w = threadIdx.x >> 5;
    #pragma unroll
    for (int o = 16; o > 0; o >>= 1) v = fmaxf(v, __shfl_down_sync(0xffffffffu, v, o));
    if (lane == 0) sh[w] = v;
    __syncthreads();
    int nw = blockDim.x >> 5;
    v = (threadIdx.x < nw) ? sh[threadIdx.x] : -INFINITY;
    if (w == 0) {
        #pragma unroll
        for (int o = 16; o > 0; o >>= 1) v = fmaxf(v, __shfl_down_sync(0xffffffffu, v, o));
        if (lane == 0) sh[0] = v;
    }
    __syncthreads();
    return sh[0];
}

// ---------------- row RMSNorm over D=2048, writes both scaled variants ----------------
__global__ void rmsnorm2_kernel(const float* __restrict__ x,
                                const float* __restrict__ gq,
                                const float* __restrict__ gkv) {
    int row = blockIdx.x;
    const float* xr = x + (size_t)row * DD;
    float s = 0.0f;
    for (int c = threadIdx.x; c < DD; c += blockDim.x) { float v = xr[c]; s += v * v; }
    __shared__ float sh[32];
    s = blockReduceSum(s, sh);
    float inv = rsqrtf(s * (1.0f / DD) + EPSV);
    for (int c = threadIdx.x; c < DD; c += blockDim.x) {
        float v = xr[c] * inv;
        d_xqn [(size_t)row * DD + c] = v * gq[c];
        d_xkvn[(size_t)row * DD + c] = v * gkv[c];
    }
}

// ---------------- per-head RMSNorm on q,k + relayout to [B,H,T,d]; v copy ----------------
__global__ void head_rms_kernel(const float* __restrict__ ghead) {
    int bid = blockIdx.x;              // ((b*H + h)*T + t)
    int t  = bid & (TT - 1);
    int bh = bid / TT;
    int h  = bh & (HH - 1);
    int b  = bh / HH;
    int bt = b * TT + t;
    int i  = threadIdx.x;              // 128 threads = d

    float qv = d_qlin[(size_t)bt * DD + h * HD + i];
    size_t ko = (size_t)bt * (2 * DD) + h * HD + i;
    float kv = d_kvlin[ko];
    float vv = d_kvlin[ko + DD];

    __shared__ float sh[32];
    float sq = blockReduceSum(qv * qv, sh);
    float sk = blockReduceSum(kv * kv, sh);

    float g = ghead[i];
    size_t oo = (size_t)bid * HD + i;
    d_qn[oo] = qv * rsqrtf(sq * (1.0f / HD) + EPSV) * g;
    d_kn[oo] = kv * rsqrtf(sk * (1.0f / HD) + EPSV) * g;
    d_vt[oo] = vv;
}

// ---------------- batched GEMM: C = alpha * A@B(+bias). 128x128x16, 8x8/thread ----------------
// A: [M,K] row-major, lda. B: if !TRANSB [K,N] ldb row-major; if TRANSB element(k,n)=B[n*ldb+k].
// grid = (N/128, M/128, batches). All dims must divide evenly (they do here).
template<bool TRANSB, bool HAS_BIAS>
__global__ __launch_bounds__(256, 2)
void gemm128(const float* __restrict__ Ag, const float* __restrict__ Bg,
             const float* __restrict__ bias, float* __restrict__ Cg,
             int K, int lda, int ldb, int ldc,
             size_t sA, size_t sB, size_t sC, float alpha) {
    const float* A = Ag + (size_t)blockIdx.z * sA;
    const float* B = Bg + (size_t)blockIdx.z * sB;
    float*       C = Cg + (size_t)blockIdx.z * sC;

    __shared__ float As[16][128];   // [k][m]
    __shared__ float Bs[16][128];   // [k][n]

    const int tid = threadIdx.x;
    const int tx = tid & 15, ty = tid >> 4;
    const int bm = blockIdx.y * 128, bn = blockIdx.x * 128;

    float acc[8][8];
    #pragma unroll
    for (int i = 0; i < 8; i++)
        #pragma unroll
        for (int j = 0; j < 8; j++) acc[i][j] = 0.0f;

    for (int k0 = 0; k0 < K; k0 += 16) {
        // A tile: 128 rows x 16 k, float4 along k
        #pragma unroll
        for (int it = 0; it < 2; it++) {
            int f = tid + it * 256;
            int row = f & 127, k4 = f >> 7;
            float4 v = *(const float4*)(A + (size_t)(bm + row) * lda + k0 + k4 * 4);
            As[k4 * 4 + 0][row] = v.x; As[k4 * 4 + 1][row] = v.y;
            As[k4 * 4 + 2][row] = v.z; As[k4 * 4 + 3][row] = v.w;
        }
        if (!TRANSB) {
            #pragma unroll
            for (int it = 0; it < 2; it++) {
                int f = tid + it * 256;
                int c4 = f & 31, kr = f >> 5;
                *(float4*)&Bs[kr][c4 * 4] =
                    *(const float4*)(B + (size_t)(k0 + kr) * ldb + bn + c4 * 4);
            }
        } else {
            #pragma unroll
            for (int it = 0; it < 2; it++) {
                int f = tid + it * 256;
                int n = f & 127, k4 = f >> 7;
                float4 v = *(const float4*)(B + (size_t)(bn + n) * ldb + k0 + k4 * 4);
                Bs[k4 * 4 + 0][n] = v.x; Bs[k4 * 4 + 1][n] = v.y;
                Bs[k4 * 4 + 2][n] = v.z; Bs[k4 * 4 + 3][n] = v.w;
            }
        }
        __syncthreads();
        #pragma unroll
        for (int kk = 0; kk < 16; kk++) {
            float4 a0 = *(const float4*)&As[kk][ty * 4];
            float4 a1 = *(const float4*)&As[kk][64 + ty * 4];
            float4 b0 = *(const float4*)&Bs[kk][tx * 4];
            float4 b1 = *(const float4*)&Bs[kk][64 + tx * 4];
            float ar[8] = {a0.x, a0.y, a0.z, a0.w, a1.x, a1.y, a1.z, a1.w};
            float br[8] = {b0.x, b0.y, b0.z, b0.w, b1.x, b1.y, b1.z, b1.w};
            #pragma unroll
            for (int i = 0; i < 8; i++)
                #pragma unroll
                for (int j = 0; j < 8; j++)
                    acc[i][j] = fmaf(ar[i], br[j], acc[i][j]);
        }
        __syncthreads();
    }

    #pragma unroll
    for (int i = 0; i < 8; i++) {
        int m = bm + ((i < 4) ? (ty * 4 + i) : (64 + ty * 4 + (i - 4)));
        float* crow = C + (size_t)m * ldc;
        #pragma unroll
        for (int half = 0; half < 2; half++) {
            int n0 = bn + half * 64 + tx * 4;
            const float* a = &acc[i][half * 4];
            float4 o;
            o.x = a[0] * alpha; o.y = a[1] * alpha; o.z = a[2] * alpha; o.w = a[3] * alpha;
            if (HAS_BIAS) {
                o.x += bias[n0 + 0]; o.y += bias[n0 + 1];
                o.z += bias[n0 + 2]; o.w += bias[n0 + 3];
            }
            *(float4*)(crow + n0) = o;
        }
    }
}

// ---------------- row softmax over T=2048, in-place on d_sc ----------------
__global__ void softmax_rows_kernel() {
    size_t row = blockIdx.x;
    float* s = d_sc + row * TT;
    __shared__ float sh[32];
    float m = -INFINITY;
    for (int c = threadIdx.x; c < TT; c += blockDim.x) m = fmaxf(m, s[c]);
    m = blockReduceMax(m, sh);
    float sum = 0.0f;
    for (int c = threadIdx.x; c < TT; c += blockDim.x) {
        float e = __expf(s[c] - m);
        s[c] = e;
        sum += e;
    }
    sum = blockReduceSum(sum, sh);
    float inv = 1.0f / sum;
    for (int c = threadIdx.x; c < TT; c += blockDim.x) s[c] *= inv;
}

// ---------------- [B,H,T,d] -> [B*T, D] ----------------
__global__ void wv_transpose_kernel() {
    int idx = blockIdx.x * blockDim.x + threadIdx.x;   // 8388608 total
    int i = idx & (HD - 1);
    int t = (idx >> 7) & (TT - 1);
    int h = (idx >> 18) & (HH - 1);
    int b = idx >> 22;
    d_wvt[((size_t)(b * TT + t)) * DD + h * HD + i] = d_wv[idx];
}

// ---------------- launch ----------------
static float* symaddr(const void* sym) {
    void* p = nullptr;
    cudaGetSymbolAddress(&p, sym);
    return (float*)p;
}

extern "C" void kernel_launch(void* const* d_in, const int* in_sizes, int n_in,
                              void* d_out, int out_size) {
    const float* x   = (const float*)d_in[0];
    const float* gq  = (const float*)d_in[1];
    const float* Wq  = (const float*)d_in[2];
    const float* bq  = (const float*)d_in[3];
    const float* gkv = (const float*)d_in[4];
    const float* Wkv = (const float*)d_in[5];
    const float* bkv = (const float*)d_in[6];
    const float* gh  = (const float*)d_in[7];
    const float* Wo  = (const float*)d_in[8];
    const float* bo  = (const float*)d_in[9];
    float* out = (float*)d_out;

    float* xqn  = symaddr(d_xqn);
    float* xkvn = symaddr(d_xkvn);
    float* qlin = symaddr(d_qlin);
    float* kvlin= symaddr(d_kvlin);
    float* qn   = symaddr(d_qn);
    float* kn   = symaddr(d_kn);
    float* vt   = symaddr(d_vt);
    float* sc   = symaddr(d_sc);
    float* wv   = symaddr(d_wv);
    float* wvt  = symaddr(d_wvt);

    const float scale = 0.088388347648318447f;   // 1/sqrt(128)

    // 1. row RMSNorm (both branches)
    rmsnorm2_kernel<<<ROWS, 256>>>(x, gq, gkv);

    // 2. q = xqn @ Wq + bq   [4096,2048]x[2048,2048]
    gemm128<false, true><<<dim3(16, 32, 1), 256>>>(
        xqn, Wq, bq, qlin, DD, DD, DD, DD, 0, 0, 0, 1.0f);

    // 3. kv = xkvn @ Wkv + bkv   [4096,2048]x[2048,4096]
    gemm128<false, true><<<dim3(32, 32, 1), 256>>>(
        xkvn, Wkv, bkv, kvlin, DD, DD, 2 * DD, 2 * DD, 0, 0, 0, 1.0f);

    // 4. per-head RMSNorm + relayout
    head_rms_kernel<<<BB * HH * TT, HD>>>(gh);

    // 5. scores = scale * qn @ kn^T   batched [2048,128]x[128,2048], 32 batches
    gemm128<true, false><<<dim3(16, 16, 32), 256>>>(
        qn, kn, nullptr, sc, HD, HD, HD, TT,
        (size_t)TT * HD, (size_t)TT * HD, (size_t)TT * TT, scale);

    // 6. softmax rows
    softmax_rows_kernel<<<BB * HH * TT, 256>>>();

    // 7. wv = attn @ v   batched [2048,2048]x[2048,128]
    gemm128<false, false><<<dim3(1, 16, 32), 256>>>(
        sc, vt, nullptr, wv, TT, TT, HD, HD,
        (size_t)TT * TT, (size_t)TT * HD, (size_t)TT * HD, 1.0f);

    // 8. relayout to [B*T, D]
    wv_transpose_kernel<<<(BB * HH * TT * HD) / 256, 256>>>();

    // 9. out = wvt @ Wo + bo
    gemm128<false, true><<<dim3(16, 32, 1), 256>>>(
        wvt, Wo, bo, out, DD, DD, DD, DD, 0, 0, 0, 1.0f);
}

// round 4
// speedup vs baseline: 2.3451x; 2.3451x over previous
#include <cuda_runtime.h>
#include <cuda_bf16.h>
#include <cstdint>
#include <math.h>

#define BB 2
#define TT 2048
#define DD 2048
#define HH 16
#define HD 128
#define ROWS (BB*TT)              // 4096
#define EPSV 1.1920929e-07f
#define ATT_SCALE 0.088388347648318447f   // 1/sqrt(128)

typedef __nv_bfloat16 bf16;

// ---------------- scratch (device globals) ----------------
__device__ __align__(256) bf16 d_xq_h [ROWS*DD], d_xq_l [ROWS*DD];
__device__ __align__(256) bf16 d_xkv_h[ROWS*DD], d_xkv_l[ROWS*DD];
__device__ __align__(256) bf16 d_wq_h [DD*DD],   d_wq_l [DD*DD];     // [N,K]
__device__ __align__(256) bf16 d_wkv_h[2*DD*DD], d_wkv_l[2*DD*DD];
__device__ __align__(256) bf16 d_wo_h [DD*DD],   d_wo_l [DD*DD];
__device__ __align__(256) float d_qlin [ROWS*DD];
__device__ __align__(256) float d_kvlin[ROWS*2*DD];
__device__ __align__(256) bf16 d_qn_h[BB*HH*TT*HD], d_qn_l[BB*HH*TT*HD]; // [B,H,T,d]
__device__ __align__(256) bf16 d_kn_h[BB*HH*TT*HD], d_kn_l[BB*HH*TT*HD];
__device__ __align__(256) bf16 d_vt_h[BB*HH*HD*TT], d_vt_l[BB*HH*HD*TT]; // [B,H,d,T]
__device__ __align__(256) float d_sc[(size_t)BB*HH*TT*TT];               // 537MB
__device__ __align__(256) bf16 d_p_h[(size_t)BB*HH*TT*TT], d_p_l[(size_t)BB*HH*TT*TT];
__device__ __align__(256) float d_wv[BB*HH*TT*HD];                       // [B,H,T,d]
__device__ __align__(256) bf16 d_wvt_h[ROWS*DD], d_wvt_l[ROWS*DD];       // [B*T, D]

// ---------------- helpers ----------------
__device__ __forceinline__ void split2(float x, bf16& h, bf16& l) {
    h = __float2bfloat16(x);
    l = __float2bfloat16(x - __bfloat162float(h));
}

__device__ __forceinline__ float blockReduceSum(float v, float* sh) {
    __syncthreads();
    int lane = threadIdx.x & 31, w = threadIdx.x >> 5;
    #pragma unroll
    for (int o = 16; o > 0; o >>= 1) v += __shfl_down_sync(0xffffffffu, v, o);
    if (lane == 0) sh[w] = v;
    __syncthreads();
    int nw = blockDim.x >> 5;
    v = (threadIdx.x < nw) ? sh[threadIdx.x] : 0.0f;
    if (w == 0) {
        #pragma unroll
        for (int o = 16; o > 0; o >>= 1) v += __shfl_down_sync(0xffffffffu, v, o);
        if (lane == 0) sh[0] = v;
    }
    __syncthreads();
    return sh[0];
}

__device__ __forceinline__ float blockReduceMax(float v, float* sh) {
    __syncthreads();
    int lane = threadIdx.x & 31, w = threadIdx.x >> 5;
    #pragma unroll
    for (int o = 16; o > 0; o >>= 1) v = fmaxf(v, __shfl_down_sync(0xffffffffu, v, o));
    if (lane == 0) sh[w] = v;
    __syncthreads();
    int nw = blockDim.x >> 5;
    v = (threadIdx.x < nw) ? sh[threadIdx.x] : -INFINITY;
    if (w == 0) {
        #pragma unroll
        for (int o = 16; o > 0; o >>= 1) v = fmaxf(v, __shfl_down_sync(0xffffffffu, v, o));
        if (lane == 0) sh[0] = v;
    }
    __syncthreads();
    return sh[0];
}

__device__ __forceinline__ uint32_t smem_u32(const void* p) {
    return (uint32_t)__cvta_generic_to_shared(p);
}

__device__ __forceinline__ void ldsm4(uint32_t addr, uint32_t* r) {
    asm volatile("ldmatrix.sync.aligned.m8n8.x4.shared.b16 {%0,%1,%2,%3}, [%4];"
                 : "=r"(r[0]), "=r"(r[1]), "=r"(r[2]), "=r"(r[3]) : "r"(addr));
}

__device__ __forceinline__ void mma16816(float* c, const uint32_t* a, const uint32_t* b) {
    asm volatile("mma.sync.aligned.m16n8k16.row.col.f32.bf16.bf16.f32 "
                 "{%0,%1,%2,%3}, {%4,%5,%6,%7}, {%8,%9}, {%0,%1,%2,%3};"
                 : "+f"(c[0]), "+f"(c[1]), "+f"(c[2]), "+f"(c[3])
                 : "r"(a[0]), "r"(a[1]), "r"(a[2]), "r"(a[3]), "r"(b[0]), "r"(b[1]));
}

// ---------------- mma.sync GEMM: C = alpha*(A @ Bt^T) (+bias) ----------------
// A: [M,K] row-major hi/lo bf16; Bt: [N,K] row-major hi/lo bf16. K % 64 == 0.
// Block tile 128x128, warp tile 64x32 (2x4 warps), K-stage 64, 2-stage cp.async.
#define TILE_B 16384                    // 128 rows x 128B
#define STAGE_B (4*TILE_B)              // Ah, Al, Bh, Bl
#define SMEM_DYN (2*STAGE_B)            // 131072

template<bool HAS_BIAS>
__global__ __launch_bounds__(256, 1)
void mma_gemm(const bf16* __restrict__ Ah, const bf16* __restrict__ Al,
              const bf16* __restrict__ Bh, const bf16* __restrict__ Bl,
              const float* __restrict__ bias, float* __restrict__ C,
              int K, int ldc, size_t sA, size_t sB, size_t sC, float alpha) {
    extern __shared__ char smem[];
    const uint32_t sb = smem_u32(smem);
    const int tid = threadIdx.x, lane = tid & 31, w = tid >> 5;
    const int wm = w >> 2, wn = w & 3;          // warp grid 2(M) x 4(N)
    const int bm = blockIdx.y * 128, bn = blockIdx.x * 128;
    const size_t z = blockIdx.z;

    const bf16* srcs[4];
    srcs[0] = Ah + z * sA + (size_t)bm * K;
    srcs[1] = Al + z * sA + (size_t)bm * K;
    srcs[2] = Bh + z * sB + (size_t)bn * K;
    srcs[3] = Bl + z * sB + (size_t)bn * K;

    float acc[4][4][4];
    #pragma unroll
    for (int t = 0; t < 4; t++)
        #pragma unroll
        for (int n = 0; n < 4; n++)
            #pragma unroll
            for (int r = 0; r < 4; r++) acc[t][n][r] = 0.0f;

    const int NC = K >> 6;

    auto issue_load = [&](int stage, int kc) {
        const uint32_t base = sb + stage * STAGE_B;
        const int k0 = kc << 6;
        #pragma unroll
        for (int t = 0; t < 4; t++) {
            const bf16* sp = srcs[t] + k0;
            const uint32_t tb = base + t * TILE_B;
            #pragma unroll
            for (int j = 0; j < 4; j++) {
                int f = tid + j * 256;
                int r = f >> 3, c = f & 7;
                uint32_t dst = tb + (uint32_t)(r * 128 + ((c ^ (r & 7)) << 4));
                const void* src = sp + (size_t)r * K + c * 8;
                asm volatile("cp.async.cg.shared.global [%0], [%1], 16;"
                             :: "r"(dst), "l"(src));
            }
        }
        asm volatile("cp.async.commit_group;" ::: "memory");
    };

    issue_load(0, 0);
    for (int kc = 0; kc < NC; kc++) {
        const int cur = kc & 1;
        if (kc + 1 < NC) {
            issue_load(cur ^ 1, kc + 1);
            asm volatile("cp.async.wait_group 1;" ::: "memory");
        } else {
            asm volatile("cp.async.wait_group 0;" ::: "memory");
        }
        __syncthreads();

        const uint32_t base = sb + cur * STAGE_B;
        #pragma unroll
        for (int s = 0; s < 4; s++) {           // four k16 steps in the k64 stage
            uint32_t aH[4][4], aL[4][4], bH[4][2], bL[4][2];
            #pragma unroll
            for (int t = 0; t < 4; t++) {
                int m = wm * 64 + t * 16 + (lane & 15);
                uint32_t off = (uint32_t)(m * 128 + (((s * 2 + (lane >> 4)) ^ (m & 7)) << 4));
                ldsm4(base + off, aH[t]);
                ldsm4(base + TILE_B + off, aL[t]);
            }
            #pragma unroll
            for (int u = 0; u < 2; u++) {
                int n = wn * 32 + u * 16 + (lane & 15);
                uint32_t off = (uint32_t)(n * 128 + (((s * 2 + (lane >> 4)) ^ (n & 7)) << 4));
                uint32_t r4[4];
                ldsm4(base + 2 * TILE_B + off, r4);
                bH[2*u][0] = r4[0]; bH[2*u+1][0] = r4[1];
                bH[2*u][1] = r4[2]; bH[2*u+1][1] = r4[3];
                ldsm4(base + 3 * TILE_B + off, r4);
                bL[2*u][0] = r4[0]; bL[2*u+1][0] = r4[1];
                bL[2*u][1] = r4[2]; bL[2*u+1][1] = r4[3];
            }
            #pragma unroll
            for (int t = 0; t < 4; t++)
                #pragma unroll
                for (int n = 0; n < 4; n++) {
                    mma16816(acc[t][n], aH[t], bH[n]);
                    mma16816(acc[t][n], aH[t], bL[n]);
                    mma16816(acc[t][n], aL[t], bH[n]);
                }
        }
        __syncthreads();
    }

    // epilogue
    float* Cz = C + z * sC;
    #pragma unroll
    for (int t = 0; t < 4; t++) {
        #pragma unroll
        for (int n = 0; n < 4; n++) {
            int m0 = bm + wm * 64 + t * 16 + (lane >> 2);
            int n0 = bn + wn * 32 + n * 8 + 2 * (lane & 3);
            float bx = 0.0f, by = 0.0f;
            if (HAS_BIAS) { bx = bias[n0]; by = bias[n0 + 1]; }
            float2 v0 = { acc[t][n][0] * alpha + bx, acc[t][n][1] * alpha + by };
            float2 v1 = { acc[t][n][2] * alpha + bx, acc[t][n][3] * alpha + by };
            *(float2*)(Cz + (size_t)m0 * ldc + n0) = v0;
            *(float2*)(Cz + (size_t)(m0 + 8) * ldc + n0) = v1;
        }
    }
}

// ---------------- row RMSNorm over D, emits hi/lo bf16 for both branches ----------------
__global__ void rmsnorm2_kernel(const float* __restrict__ x,
                                const float* __restrict__ gq,
                                const float* __restrict__ gkv) {
    int row = blockIdx.x;
    const float* xr = x + (size_t)row * DD;
    float s = 0.0f;
    for (int c = threadIdx.x; c < DD; c += blockDim.x) { float v = xr[c]; s += v * v; }
    __shared__ float sh[32];
    s = blockReduceSum(s, sh);
    float inv = rsqrtf(s * (1.0f / DD) + EPSV);
    for (int c = threadIdx.x; c < DD; c += blockDim.x) {
        float v = xr[c] * inv;
        size_t o = (size_t)row * DD + c;
        bf16 h, l;
        split2(v * gq[c], h, l);  d_xq_h[o] = h;  d_xq_l[o] = l;
        split2(v * gkv[c], h, l); d_xkv_h[o] = h; d_xkv_l[o] = l;
    }
}

// ---------------- weight transpose + split: W[K,N] fp32 -> Wt[N,K] hi/lo bf16 ----------------
__global__ void wtrans_kernel(const float* __restrict__ W, bf16* __restrict__ Th,
                              bf16* __restrict__ Tl, int Kd, int Nd) {
    __shared__ float tile[32][33];
    int k0 = blockIdx.y * 32, n0 = blockIdx.x * 32;
    for (int j = threadIdx.y; j < 32; j += 8)
        tile[j][threadIdx.x] = W[(size_t)(k0 + j) * Nd + n0 + threadIdx.x];
    __syncthreads();
    for (int j = threadIdx.y; j < 32; j += 8) {
        float v = tile[threadIdx.x][j];               // W[k0+tx][n0+j]
        bf16 h, l; split2(v, h, l);
        size_t o = (size_t)(n0 + j) * Kd + k0 + threadIdx.x;
        Th[o] = h; Tl[o] = l;
    }
}

// ---------------- per-head RMSNorm on q,k -> [B,H,T,d] hi/lo (scale folded into q) ----------------
__global__ void head_rms_kernel(const float* __restrict__ ghead) {
    int bid = blockIdx.x;                 // ((b*H + h)*T + t)
    int t = bid & (TT - 1);
    int bh = bid / TT;
    int h = bh & (HH - 1);
    int b = bh / HH;
    int bt = b * TT + t;
    int i = threadIdx.x;                  // 128 threads = d

    float qv = d_qlin[(size_t)bt * DD + h * HD + i];
    float kv = d_kvlin[(size_t)bt * (2 * DD) + h * HD + i];

    __shared__ float sh[32];
    float sq = blockReduceSum(qv * qv, sh);
    float sk = blockReduceSum(kv * kv, sh);

    float g = ghead[i];
    size_t o = (size_t)bid * HD + i;
    float qn = qv * rsqrtf(sq * (1.0f / HD) + EPSV) * g * ATT_SCALE;
    float kn = kv * rsqrtf(sk * (1.0f / HD) + EPSV) * g;
    bf16 hh, ll;
    split2(qn, hh, ll); d_qn_h[o] = hh; d_qn_l[o] = ll;
    split2(kn, hh, ll); d_kn_h[o] = hh; d_kn_l[o] = ll;
}

// ---------------- v transpose: kvlin v-part -> [B,H,d,T] hi/lo ----------------
__global__ void vtrans_kernel() {
    __shared__ float tile[32][33];
    int bh = blockIdx.z;
    int b = bh >> 4, h = bh & 15;
    int t0 = blockIdx.x * 32, i0 = blockIdx.y * 32;
    for (int j = threadIdx.y; j < 32; j += 8)
        tile[j][threadIdx.x] =
            d_kvlin[(size_t)(b * TT + t0 + j) * (2 * DD) + DD + h * HD + i0 + threadIdx.x];
    __syncthreads();
    for (int j = threadIdx.y; j < 32; j += 8) {
        float v = tile[threadIdx.x][j];               // v[t0+tx][i0+j]
        bf16 hh, ll; split2(v, hh, ll);
        size_t o = ((size_t)bh * HD + i0 + j) * TT + t0 + threadIdx.x;
        d_vt_h[o] = hh; d_vt_l[o] = ll;
    }
}

// ---------------- softmax rows (T=2048), fp32 in -> hi/lo bf16 probs ----------------
__global__ void softmax_kernel() {
    size_t row = blockIdx.x;
    const float* s = d_sc + row * TT;
    bf16* ph = d_p_h + row * TT;
    bf16* pl = d_p_l + row * TT;
    float r[8];
    float m = -INFINITY;
    #pragma unroll
    for (int j = 0; j < 8; j++) { r[j] = s[threadIdx.x + j * 256]; m = fmaxf(m, r[j]); }
    __shared__ float sh[32];
    m = blockReduceMax(m, sh);
    float sum = 0.0f;
    #pragma unroll
    for (int j = 0; j < 8; j++) { r[j] = __expf(r[j] - m); sum += r[j]; }
    sum = blockReduceSum(sum, sh);
    float inv = 1.0f / sum;
    #pragma unroll
    for (int j = 0; j < 8; j++) {
        bf16 h, l; split2(r[j] * inv, h, l);
        ph[threadIdx.x + j * 256] = h;
        pl[threadIdx.x + j * 256] = l;
    }
}

// ---------------- wv [B,H,T,d] fp32 -> wvt [B*T, D] hi/lo ----------------
__global__ void wvtrans_kernel() {
    int idx = blockIdx.x * blockDim.x + threadIdx.x;
    int i = idx & (HD - 1);
    int t = (idx >> 7) & (TT - 1);
    int h = (idx >> 18) & (HH - 1);
    int b = idx >> 22;
    float v = d_wv[idx];
    bf16 hh, ll; split2(v, hh, ll);
    size_t o = ((size_t)(b * TT + t)) * DD + h * HD + i;
    d_wvt_h[o] = hh; d_wvt_l[o] = ll;
}

// ---------------- launch ----------------
template<typename T> static T* symaddr(const void* sym) {
    void* p = nullptr;
    cudaGetSymbolAddress(&p, sym);
    return (T*)p;
}

extern "C" void kernel_launch(void* const* d_in, const int* in_sizes, int n_in,
                              void* d_out, int out_size) {
    const float* x   = (const float*)d_in[0];
    const float* gq  = (const float*)d_in[1];
    const float* Wq  = (const float*)d_in[2];
    const float* bq  = (const float*)d_in[3];
    const float* gkv = (const float*)d_in[4];
    const float* Wkv = (const float*)d_in[5];
    const float* bkv = (const float*)d_in[6];
    const float* gh  = (const float*)d_in[7];
    const float* Wo  = (const float*)d_in[8];
    const float* bo  = (const float*)d_in[9];
    float* out = (float*)d_out;

    bf16* xq_h  = symaddr<bf16>(d_xq_h);   bf16* xq_l  = symaddr<bf16>(d_xq_l);
    bf16* xkv_h = symaddr<bf16>(d_xkv_h);  bf16* xkv_l = symaddr<bf16>(d_xkv_l);
    bf16* wq_h  = symaddr<bf16>(d_wq_h);   bf16* wq_l  = symaddr<bf16>(d_wq_l);
    bf16* wkv_h = symaddr<bf16>(d_wkv_h);  bf16* wkv_l = symaddr<bf16>(d_wkv_l);
    bf16* wo_h  = symaddr<bf16>(d_wo_h);   bf16* wo_l  = symaddr<bf16>(d_wo_l);
    float* qlin = symaddr<float>(d_qlin);
    float* kvlin= symaddr<float>(d_kvlin);
    bf16* qn_h  = symaddr<bf16>(d_qn_h);   bf16* qn_l  = symaddr<bf16>(d_qn_l);
    bf16* kn_h  = symaddr<bf16>(d_kn_h);   bf16* kn_l  = symaddr<bf16>(d_kn_l);
    bf16* vt_h  = symaddr<bf16>(d_vt_h);   bf16* vt_l  = symaddr<bf16>(d_vt_l);
    float* sc   = symaddr<float>(d_sc);
    bf16* p_h   = symaddr<bf16>(d_p_h);    bf16* p_l   = symaddr<bf16>(d_p_l);
    float* wv   = symaddr<float>(d_wv);
    bf16* wvt_h = symaddr<bf16>(d_wvt_h);  bf16* wvt_l = symaddr<bf16>(d_wvt_l);

    cudaFuncSetAttribute(mma_gemm<true>,  cudaFuncAttributeMaxDynamicSharedMemorySize, SMEM_DYN);
    cudaFuncSetAttribute(mma_gemm<false>, cudaFuncAttributeMaxDynamicSharedMemorySize, SMEM_DYN);

    // 1. RMSNorm (both branches) -> hi/lo
    rmsnorm2_kernel<<<ROWS, 256>>>(x, gq, gkv);

    // 2. weight transpose + split
    wtrans_kernel<<<dim3(DD / 32, DD / 32), dim3(32, 8)>>>(Wq, wq_h, wq_l, DD, DD);
    wtrans_kernel<<<dim3(2 * DD / 32, DD / 32), dim3(32, 8)>>>(Wkv, wkv_h, wkv_l, DD, 2 * DD);
    wtrans_kernel<<<dim3(DD / 32, DD / 32), dim3(32, 8)>>>(Wo, wo_h, wo_l, DD, DD);

    // 3. Q projection: [4096,2048] x [2048,2048]^T
    mma_gemm<true><<<dim3(16, 32, 1), 256, SMEM_DYN>>>(
        xq_h, xq_l, wq_h, wq_l, bq, qlin, DD, DD, 0, 0, 0, 1.0f);

    // 4. KV projection: [4096,2048] x [4096,2048]^T
    mma_gemm<true><<<dim3(32, 32, 1), 256, SMEM_DYN>>>(
        xkv_h, xkv_l, wkv_h, wkv_l, bkv, kvlin, DD, 2 * DD, 0, 0, 0, 1.0f);

    // 5. per-head RMSNorm -> qn/kn hi/lo; v transpose -> vt hi/lo
    head_rms_kernel<<<BB * HH * TT, HD>>>(gh);
    vtrans_kernel<<<dim3(TT / 32, HD / 32, BB * HH), dim3(32, 8)>>>();

    // 6. scores = qn @ kn^T (scale folded into qn): batched 32x [2048,128]x[2048,128]^T
    mma_gemm<false><<<dim3(16, 16, 32), 256, SMEM_DYN>>>(
        qn_h, qn_l, kn_h, kn_l, nullptr, sc, HD, TT,
        (size_t)TT * HD, (size_t)TT * HD, (size_t)TT * TT, 1.0f);

    // 7. softmax -> probs hi/lo
    softmax_kernel<<<BB * HH * TT, 256>>>();

    // 8. wv = probs @ vt^T: batched 32x [2048,2048]x[128,2048]^T
    mma_gemm<false><<<dim3(1, 16, 32), 256, SMEM_DYN>>>(
        p_h, p_l, vt_h, vt_l, nullptr, wv, TT, HD,
        (size_t)TT * TT, (size_t)HD * TT, (size_t)TT * HD, 1.0f);

    // 9. relayout + split
    wvtrans_kernel<<<(BB * HH * TT * HD) / 256, 256>>>();

    // 10. out = wvt @ Wo^T + bo
    mma_gemm<true><<<dim3(16, 32, 1), 256, SMEM_DYN>>>(
        wvt_h, wvt_l, wo_h, wo_l, bo, out, DD, DD, 0, 0, 0, 1.0f);
}

// round 5
// speedup vs baseline: 2.6582x; 1.1335x over previous
#include <cuda_runtime.h>
#include <cuda_bf16.h>
#include <cstdint>
#include <math.h>

#define BB 2
#define TT 2048
#define DD 2048
#define HH 16
#define HD 128
#define ROWS (BB*TT)              // 4096
#define EPSV 1.1920929e-07f
#define ATT_SCALE 0.088388347648318447f   // 1/sqrt(128)

typedef __nv_bfloat16 bf16;

// ---------------- scratch (device globals) ----------------
__device__ __align__(256) bf16 d_xq_h [ROWS*DD], d_xq_l [ROWS*DD];
__device__ __align__(256) bf16 d_xkv_h[ROWS*DD], d_xkv_l[ROWS*DD];
__device__ __align__(256) bf16 d_wq_h [DD*DD],   d_wq_l [DD*DD];     // [N,K]
__device__ __align__(256) bf16 d_wkv_h[2*DD*DD], d_wkv_l[2*DD*DD];
__device__ __align__(256) bf16 d_wo_h [DD*DD],   d_wo_l [DD*DD];
__device__ __align__(256) float d_qlin [ROWS*DD];
__device__ __align__(256) float d_kvlin[ROWS*2*DD];
__device__ __align__(256) bf16 d_qn_h[BB*HH*TT*HD], d_qn_l[BB*HH*TT*HD]; // [B,H,T,d]
__device__ __align__(256) bf16 d_kn_h[BB*HH*TT*HD], d_kn_l[BB*HH*TT*HD];
__device__ __align__(256) bf16 d_vt_h[BB*HH*HD*TT], d_vt_l[BB*HH*HD*TT]; // [B,H,d,T]
__device__ __align__(256) bf16 d_wvt_h[ROWS*DD], d_wvt_l[ROWS*DD];       // [B*T, D]

// ---------------- helpers ----------------
__device__ __forceinline__ void split2(float x, bf16& h, bf16& l) {
    h = __float2bfloat16(x);
    l = __float2bfloat16(x - __bfloat162float(h));
}

__device__ __forceinline__ uint32_t pack_bf2(bf16 a, bf16 b) {
    __nv_bfloat162 t = __halves2bfloat162(a, b);
    return *(uint32_t*)&t;
}

__device__ __forceinline__ float blockReduceSum(float v, float* sh) {
    __syncthreads();
    int lane = threadIdx.x & 31, w = threadIdx.x >> 5;
    #pragma unroll
    for (int o = 16; o > 0; o >>= 1) v += __shfl_down_sync(0xffffffffu, v, o);
    if (lane == 0) sh[w] = v;
    __syncthreads();
    int nw = blockDim.x >> 5;
    v = (threadIdx.x < nw) ? sh[threadIdx.x] : 0.0f;
    if (w == 0) {
        #pragma unroll
        for (int o = 16; o > 0; o >>= 1) v += __shfl_down_sync(0xffffffffu, v, o);
        if (lane == 0) sh[0] = v;
    }
    __syncthreads();
    return sh[0];
}

__device__ __forceinline__ uint32_t smem_u32(const void* p) {
    return (uint32_t)__cvta_generic_to_shared(p);
}

__device__ __forceinline__ void ldsm4(uint32_t addr, uint32_t* r) {
    asm volatile("ldmatrix.sync.aligned.m8n8.x4.shared.b16 {%0,%1,%2,%3}, [%4];"
                 : "=r"(r[0]), "=r"(r[1]), "=r"(r[2]), "=r"(r[3]) : "r"(addr));
}

__device__ __forceinline__ void mma16816(float* c, const uint32_t* a, const uint32_t* b) {
    asm volatile("mma.sync.aligned.m16n8k16.row.col.f32.bf16.bf16.f32 "
                 "{%0,%1,%2,%3}, {%4,%5,%6,%7}, {%8,%9}, {%0,%1,%2,%3};"
                 : "+f"(c[0]), "+f"(c[1]), "+f"(c[2]), "+f"(c[3])
                 : "r"(a[0]), "r"(a[1]), "r"(a[2]), "r"(a[3]), "r"(b[0]), "r"(b[1]));
}

__device__ __forceinline__ void cpasync16(uint32_t dst, const void* src) {
    asm volatile("cp.async.cg.shared.global [%0], [%1], 16;" :: "r"(dst), "l"(src));
}
__device__ __forceinline__ void cpcommit() {
    asm volatile("cp.async.commit_group;" ::: "memory");
}
template<int N> __device__ __forceinline__ void cpwait() {
    asm volatile("cp.async.wait_group %0;" :: "n"(N) : "memory");
}

// ---------------- mma.sync GEMM (unchanged from round 4) ----------------
#define TILE_B 16384
#define STAGE_B (4*TILE_B)
#define SMEM_DYN (2*STAGE_B)

template<bool HAS_BIAS>
__global__ __launch_bounds__(256, 1)
void mma_gemm(const bf16* __restrict__ Ah, const bf16* __restrict__ Al,
              const bf16* __restrict__ Bh, const bf16* __restrict__ Bl,
              const float* __restrict__ bias, float* __restrict__ C,
              int K, int ldc, size_t sA, size_t sB, size_t sC, float alpha) {
    extern __shared__ char smem[];
    const uint32_t sb = smem_u32(smem);
    const int tid = threadIdx.x, lane = tid & 31, w = tid >> 5;
    const int wm = w >> 2, wn = w & 3;
    const int bm = blockIdx.y * 128, bn = blockIdx.x * 128;
    const size_t z = blockIdx.z;

    const bf16* srcs[4];
    srcs[0] = Ah + z * sA + (size_t)bm * K;
    srcs[1] = Al + z * sA + (size_t)bm * K;
    srcs[2] = Bh + z * sB + (size_t)bn * K;
    srcs[3] = Bl + z * sB + (size_t)bn * K;

    float acc[4][4][4];
    #pragma unroll
    for (int t = 0; t < 4; t++)
        #pragma unroll
        for (int n = 0; n < 4; n++)
            #pragma unroll
            for (int r = 0; r < 4; r++) acc[t][n][r] = 0.0f;

    const int NC = K >> 6;

    auto issue_load = [&](int stage, int kc) {
        const uint32_t base = sb + stage * STAGE_B;
        const int k0 = kc << 6;
        #pragma unroll
        for (int t = 0; t < 4; t++) {
            const bf16* sp = srcs[t] + k0;
            const uint32_t tb = base + t * TILE_B;
            #pragma unroll
            for (int j = 0; j < 4; j++) {
                int f = tid + j * 256;
                int r = f >> 3, c = f & 7;
                uint32_t dst = tb + (uint32_t)(r * 128 + ((c ^ (r & 7)) << 4));
                cpasync16(dst, sp + (size_t)r * K + c * 8);
            }
        }
        cpcommit();
    };

    issue_load(0, 0);
    for (int kc = 0; kc < NC; kc++) {
        const int cur = kc & 1;
        if (kc + 1 < NC) { issue_load(cur ^ 1, kc + 1); cpwait<1>(); }
        else             { cpwait<0>(); }
        __syncthreads();

        const uint32_t base = sb + cur * STAGE_B;
        #pragma unroll
        for (int s = 0; s < 4; s++) {
            uint32_t aH[4][4], aL[4][4], bH[4][2], bL[4][2];
            #pragma unroll
            for (int t = 0; t < 4; t++) {
                int m = wm * 64 + t * 16 + (lane & 15);
                uint32_t off = (uint32_t)(m * 128 + (((s * 2 + (lane >> 4)) ^ (m & 7)) << 4));
                ldsm4(base + off, aH[t]);
                ldsm4(base + TILE_B + off, aL[t]);
            }
            #pragma unroll
            for (int u = 0; u < 2; u++) {
                int n = wn * 32 + u * 16 + (lane & 15);
                uint32_t off = (uint32_t)(n * 128 + (((s * 2 + (lane >> 4)) ^ (n & 7)) << 4));
                uint32_t r4[4];
                ldsm4(base + 2 * TILE_B + off, r4);
                bH[2*u][0] = r4[0]; bH[2*u+1][0] = r4[1];
                bH[2*u][1] = r4[2]; bH[2*u+1][1] = r4[3];
                ldsm4(base + 3 * TILE_B + off, r4);
                bL[2*u][0] = r4[0]; bL[2*u+1][0] = r4[1];
                bL[2*u][1] = r4[2]; bL[2*u+1][1] = r4[3];
            }
            #pragma unroll
            for (int t = 0; t < 4; t++)
                #pragma unroll
                for (int n = 0; n < 4; n++) {
                    mma16816(acc[t][n], aH[t], bH[n]);
                    mma16816(acc[t][n], aH[t], bL[n]);
                    mma16816(acc[t][n], aL[t], bH[n]);
                }
        }
        __syncthreads();
    }

    float* Cz = C + z * sC;
    #pragma unroll
    for (int t = 0; t < 4; t++) {
        #pragma unroll
        for (int n = 0; n < 4; n++) {
            int m0 = bm + wm * 64 + t * 16 + (lane >> 2);
            int n0 = bn + wn * 32 + n * 8 + 2 * (lane & 3);
            float bx = 0.0f, by = 0.0f;
            if (HAS_BIAS) { bx = bias[n0]; by = bias[n0 + 1]; }
            float2 v0 = { acc[t][n][0] * alpha + bx, acc[t][n][1] * alpha + by };
            float2 v1 = { acc[t][n][2] * alpha + bx, acc[t][n][3] * alpha + by };
            *(float2*)(Cz + (size_t)m0 * ldc + n0) = v0;
            *(float2*)(Cz + (size_t)(m0 + 8) * ldc + n0) = v1;
        }
    }
}

// ---------------- fused flash attention ----------------
// grid (T/128, B*H), 256 threads (8 warps x 16 q-rows). smem: Kh|Kl|Vh|Vl|Qh|Ql 32KB each.
// Tiles are [128 rows x 128 elems] bf16, 256B rows, XOR-swizzled.
#define FSEG 32768
#define SMEM_FLASH (6*FSEG)             // 196608

__device__ __forceinline__ uint32_t swz(int r, int c) {
    return (uint32_t)(r * 256 + (((c & 8) | ((c ^ r) & 7)) << 4));
}

__global__ __launch_bounds__(256, 1)
void flash_kernel() {
    extern __shared__ char smem[];
    const uint32_t sb = smem_u32(smem);
    const uint32_t sKh = sb, sKl = sb + FSEG, sVh = sb + 2*FSEG, sVl = sb + 3*FSEG;
    const uint32_t sQh = sb + 4*FSEG, sQl = sb + 5*FSEG;

    const int tid = threadIdx.x, lane = tid & 31, w = tid >> 5;
    const int bh = blockIdx.y;
    const int q0 = blockIdx.x * 128;

    const bf16* qh = d_qn_h + (size_t)bh * TT * HD + (size_t)q0 * HD;
    const bf16* ql = d_qn_l + (size_t)bh * TT * HD + (size_t)q0 * HD;
    const bf16* kh = d_kn_h + (size_t)bh * TT * HD;
    const bf16* kl = d_kn_l + (size_t)bh * TT * HD;
    const bf16* vh = d_vt_h + (size_t)bh * HD * TT;
    const bf16* vl = d_vt_l + (size_t)bh * HD * TT;

    // tile loaders: 128 rows x 16 chunks of 16B, 2048 chunks / 256 thr = 8 iters
    auto loadT = [&](uint32_t dstb, const bf16* src, int rowStride) {
        #pragma unroll
        for (int j = 0; j < 8; j++) {
            int f = tid + j * 256;
            int r = f >> 4, c = f & 15;
            cpasync16(dstb + swz(r, c), src + (size_t)r * rowStride + c * 8);
        }
    };

    // prologue: Q + K0 + V0
    loadT(sQh, qh, HD); loadT(sQl, ql, HD);
    loadT(sKh, kh, HD); loadT(sKl, kl, HD);
    loadT(sVh, vh, TT); loadT(sVl, vl, TT);
    cpcommit();
    cpwait<0>();
    __syncthreads();

    float o[16][4];
    #pragma unroll
    for (int f = 0; f < 16; f++)
        #pragma unroll
        for (int j = 0; j < 4; j++) o[f][j] = 0.0f;
    float mrow[2] = {-INFINITY, -INFINITY};
    float lrow[2] = {0.0f, 0.0f};

    const int NT = TT / 128;
    for (int i = 0; i < NT; i++) {
        // ---- S = Q @ K(i)^T ----
        float sacc[16][4];
        #pragma unroll
        for (int f = 0; f < 16; f++)
            #pragma unroll
            for (int j = 0; j < 4; j++) sacc[f][j] = 0.0f;

        #pragma unroll
        for (int s = 0; s < 8; s++) {
            const int mR = (w << 4) + (lane & 15);
            const int cc = 2 * s + (lane >> 4);
            uint32_t aH[4], aL[4];
            ldsm4(sQh + swz(mR, cc), aH);
            ldsm4(sQl + swz(mR, cc), aL);
            #pragma unroll
            for (int u = 0; u < 8; u++) {
                const int n = u * 16 + (lane & 15);
                uint32_t r4h[4], r4l[4];
                ldsm4(sKh + swz(n, cc), r4h);
                ldsm4(sKl + swz(n, cc), r4l);
                uint32_t b0h[2] = {r4h[0], r4h[2]}, b1h[2] = {r4h[1], r4h[3]};
                uint32_t b0l[2] = {r4l[0], r4l[2]}, b1l[2] = {r4l[1], r4l[3]};
                mma16816(sacc[2*u],   aH, b0h);
                mma16816(sacc[2*u],   aH, b0l);
                mma16816(sacc[2*u],   aL, b0h);
                mma16816(sacc[2*u+1], aH, b1h);
                mma16816(sacc[2*u+1], aH, b1l);
                mma16816(sacc[2*u+1], aL, b1h);
            }
        }
        __syncthreads();                        // everyone done reading K(i)
        if (i + 1 < NT) { loadT(sKh, kh + (size_t)(i+1)*128*HD, HD);
                          loadT(sKl, kl + (size_t)(i+1)*128*HD, HD); cpcommit(); }

        // ---- online softmax ----
        float mnew[2] = {mrow[0], mrow[1]};
        #pragma unroll
        for (int f = 0; f < 16; f++) {
            mnew[0] = fmaxf(mnew[0], fmaxf(sacc[f][0], sacc[f][1]));
            mnew[1] = fmaxf(mnew[1], fmaxf(sacc[f][2], sacc[f][3]));
        }
        #pragma unroll
        for (int rr = 0; rr < 2; rr++) {
            mnew[rr] = fmaxf(mnew[rr], __shfl_xor_sync(0xffffffffu, mnew[rr], 1));
            mnew[rr] = fmaxf(mnew[rr], __shfl_xor_sync(0xffffffffu, mnew[rr], 2));
        }
        float resc[2] = { __expf(mrow[0] - mnew[0]), __expf(mrow[1] - mnew[1]) };
        mrow[0] = mnew[0]; mrow[1] = mnew[1];
        float psum[2] = {0.0f, 0.0f};
        #pragma unroll
        for (int f = 0; f < 16; f++) {
            sacc[f][0] = __expf(sacc[f][0] - mrow[0]);
            sacc[f][1] = __expf(sacc[f][1] - mrow[0]);
            sacc[f][2] = __expf(sacc[f][2] - mrow[1]);
            sacc[f][3] = __expf(sacc[f][3] - mrow[1]);
            psum[0] += sacc[f][0] + sacc[f][1];
            psum[1] += sacc[f][2] + sacc[f][3];
        }
        #pragma unroll
        for (int rr = 0; rr < 2; rr++) {
            psum[rr] += __shfl_xor_sync(0xffffffffu, psum[rr], 1);
            psum[rr] += __shfl_xor_sync(0xffffffffu, psum[rr], 2);
        }
        lrow[0] = lrow[0] * resc[0] + psum[0];
        lrow[1] = lrow[1] * resc[1] + psum[1];
        #pragma unroll
        for (int f = 0; f < 16; f++) {
            o[f][0] *= resc[0]; o[f][1] *= resc[0];
            o[f][2] *= resc[1]; o[f][3] *= resc[1];
        }

        // V(i) visibility: for i>0 it was committed last iteration; drain to it.
        if (i > 0) {
            if (i + 1 < NT) cpwait<1>(); else cpwait<0>();
            __syncthreads();
        }

        // ---- O += P @ V(i)  (P fragments built in-register from sacc) ----
        #pragma unroll
        for (int s = 0; s < 8; s++) {
            const int f0 = 2 * s, f1 = 2 * s + 1;
            uint32_t aPh[4], aPl[4];
            {
                bf16 h00, l00, h01, l01, h02, l02, h03, l03;
                split2(sacc[f0][0], h00, l00); split2(sacc[f0][1], h01, l01);
                split2(sacc[f0][2], h02, l02); split2(sacc[f0][3], h03, l03);
                aPh[0] = pack_bf2(h00, h01); aPh[1] = pack_bf2(h02, h03);
                aPl[0] = pack_bf2(l00, l01); aPl[1] = pack_bf2(l02, l03);
                split2(sacc[f1][0], h00, l00); split2(sacc[f1][1], h01, l01);
                split2(sacc[f1][2], h02, l02); split2(sacc[f1][3], h03, l03);
                aPh[2] = pack_bf2(h00, h01); aPh[3] = pack_bf2(h02, h03);
                aPl[2] = pack_bf2(l00, l01); aPl[3] = pack_bf2(l02, l03);
            }
            const int cc = 2 * s + (lane >> 4);
            #pragma unroll
            for (int u = 0; u < 8; u++) {
                const int n = u * 16 + (lane & 15);
                uint32_t r4h[4], r4l[4];
                ldsm4(sVh + swz(n, cc), r4h);
                ldsm4(sVl + swz(n, cc), r4l);
                uint32_t b0h[2] = {r4h[0], r4h[2]}, b1h[2] = {r4h[1], r4h[3]};
                uint32_t b0l[2] = {r4l[0], r4l[2]}, b1l[2] = {r4l[1], r4l[3]};
                mma16816(o[2*u],   aPh, b0h);
                mma16816(o[2*u],   aPh, b0l);
                mma16816(o[2*u],   aPl, b0h);
                mma16816(o[2*u+1], aPh, b1h);
                mma16816(o[2*u+1], aPh, b1l);
                mma16816(o[2*u+1], aPl, b1h);
            }
        }
        __syncthreads();                        // everyone done reading V(i)
        if (i + 1 < NT) {
            loadT(sVh, vh + (size_t)(i+1)*128, TT);
            loadT(sVl, vl + (size_t)(i+1)*128, TT);
            cpcommit();
            cpwait<1>();                        // K(i+1) arrived (V(i+1) still in flight)
            __syncthreads();
        }
    }

    // ---- epilogue: O /= l, write d_wvt hi/lo in [B*T, D] ----
    const int b = bh >> 4, h = bh & 15;
    const float inv0 = 1.0f / lrow[0], inv1 = 1.0f / lrow[1];
    const int r0 = (w << 4) + (lane >> 2);
    const size_t bt0 = (size_t)(b * TT + q0 + r0) * DD;
    const size_t bt1 = (size_t)(b * TT + q0 + r0 + 8) * DD;
    const int colb = h * HD + 2 * (lane & 3);
    #pragma unroll
    for (int f = 0; f < 16; f++) {
        const int col = colb + f * 8;
        bf16 h0, l0, h1, l1;
        split2(o[f][0] * inv0, h0, l0); split2(o[f][1] * inv0, h1, l1);
        *(uint32_t*)(d_wvt_h + bt0 + col) = pack_bf2(h0, h1);
        *(uint32_t*)(d_wvt_l + bt0 + col) = pack_bf2(l0, l1);
        split2(o[f][2] * inv1, h0, l0); split2(o[f][3] * inv1, h1, l1);
        *(uint32_t*)(d_wvt_h + bt1 + col) = pack_bf2(h0, h1);
        *(uint32_t*)(d_wvt_l + bt1 + col) = pack_bf2(l0, l1);
    }
}

// ---------------- elementwise producers ----------------
__global__ void rmsnorm2_kernel(const float* __restrict__ x,
                                const float* __restrict__ gq,
                                const float* __restrict__ gkv) {
    int row = blockIdx.x;
    const float* xr = x + (size_t)row * DD;
    float s = 0.0f;
    for (int c = threadIdx.x; c < DD; c += blockDim.x) { float v = xr[c]; s += v * v; }
    __shared__ float sh[32];
    s = blockReduceSum(s, sh);
    float inv = rsqrtf(s * (1.0f / DD) + EPSV);
    for (int c = threadIdx.x; c < DD; c += blockDim.x) {
        float v = xr[c] * inv;
        size_t o = (size_t)row * DD + c;
        bf16 h, l;
        split2(v * gq[c], h, l);  d_xq_h[o] = h;  d_xq_l[o] = l;
        split2(v * gkv[c], h, l); d_xkv_h[o] = h; d_xkv_l[o] = l;
    }
}

__global__ void wtrans_kernel(const float* __restrict__ W, bf16* __restrict__ Th,
                              bf16* __restrict__ Tl, int Kd, int Nd) {
    __shared__ float tile[32][33];
    int k0 = blockIdx.y * 32, n0 = blockIdx.x * 32;
    for (int j = threadIdx.y; j < 32; j += 8)
        tile[j][threadIdx.x] = W[(size_t)(k0 + j) * Nd + n0 + threadIdx.x];
    __syncthreads();
    for (int j = threadIdx.y; j < 32; j += 8) {
        float v = tile[threadIdx.x][j];
        bf16 h, l; split2(v, h, l);
        size_t o = (size_t)(n0 + j) * Kd + k0 + threadIdx.x;
        Th[o] = h; Tl[o] = l;
    }
}

__global__ void head_rms_kernel(const float* __restrict__ ghead) {
    int bid = blockIdx.x;
    int t = bid & (TT - 1);
    int bh = bid / TT;
    int h = bh & (HH - 1);
    int b = bh / HH;
    int bt = b * TT + t;
    int i = threadIdx.x;

    float qv = d_qlin[(size_t)bt * DD + h * HD + i];
    float kv = d_kvlin[(size_t)bt * (2 * DD) + h * HD + i];

    __shared__ float sh[32];
    float sq = blockReduceSum(qv * qv, sh);
    float sk = blockReduceSum(kv * kv, sh);

    float g = ghead[i];
    size_t o = (size_t)bid * HD + i;
    float qn = qv * rsqrtf(sq * (1.0f / HD) + EPSV) * g * ATT_SCALE;
    float kn = kv * rsqrtf(sk * (1.0f / HD) + EPSV) * g;
    bf16 hh, ll;
    split2(qn, hh, ll); d_qn_h[o] = hh; d_qn_l[o] = ll;
    split2(kn, hh, ll); d_kn_h[o] = hh; d_kn_l[o] = ll;
}

__global__ void vtrans_kernel() {
    __shared__ float tile[32][33];
    int bh = blockIdx.z;
    int b = bh >> 4, h = bh & 15;
    int t0 = blockIdx.x * 32, i0 = blockIdx.y * 32;
    for (int j = threadIdx.y; j < 32; j += 8)
        tile[j][threadIdx.x] =
            d_kvlin[(size_t)(b * TT + t0 + j) * (2 * DD) + DD + h * HD + i0 + threadIdx.x];
    __syncthreads();
    for (int j = threadIdx.y; j < 32; j += 8) {
        float v = tile[threadIdx.x][j];
        bf16 hh, ll; split2(v, hh, ll);
        size_t o = ((size_t)bh * HD + i0 + j) * TT + t0 + threadIdx.x;
        d_vt_h[o] = hh; d_vt_l[o] = ll;
    }
}

// ---------------- launch ----------------
template<typename T> static T* symaddr(const void* sym) {
    void* p = nullptr;
    cudaGetSymbolAddress(&p, sym);
    return (T*)p;
}

extern "C" void kernel_launch(void* const* d_in, const int* in_sizes, int n_in,
                              void* d_out, int out_size) {
    const float* x   = (const float*)d_in[0];
    const float* gq  = (const float*)d_in[1];
    const float* Wq  = (const float*)d_in[2];
    const float* bq  = (const float*)d_in[3];
    const float* gkv = (const float*)d_in[4];
    const float* Wkv = (const float*)d_in[5];
    const float* bkv = (const float*)d_in[6];
    const float* gh  = (const float*)d_in[7];
    const float* Wo  = (const float*)d_in[8];
    const float* bo  = (const float*)d_in[9];
    float* out = (float*)d_out;

    bf16* xq_h  = symaddr<bf16>(d_xq_h);   bf16* xq_l  = symaddr<bf16>(d_xq_l);
    bf16* xkv_h = symaddr<bf16>(d_xkv_h);  bf16* xkv_l = symaddr<bf16>(d_xkv_l);
    bf16* wq_h  = symaddr<bf16>(d_wq_h);   bf16* wq_l  = symaddr<bf16>(d_wq_l);
    bf16* wkv_h = symaddr<bf16>(d_wkv_h);  bf16* wkv_l = symaddr<bf16>(d_wkv_l);
    bf16* wo_h  = symaddr<bf16>(d_wo_h);   bf16* wo_l  = symaddr<bf16>(d_wo_l);
    float* qlin = symaddr<float>(d_qlin);
    float* kvlin= symaddr<float>(d_kvlin);
    bf16* wvt_h = symaddr<bf16>(d_wvt_h);  bf16* wvt_l = symaddr<bf16>(d_wvt_l);

    cudaFuncSetAttribute(mma_gemm<true>,  cudaFuncAttributeMaxDynamicSharedMemorySize, SMEM_DYN);
    cudaFuncSetAttribute(mma_gemm<false>, cudaFuncAttributeMaxDynamicSharedMemorySize, SMEM_DYN);
    cudaFuncSetAttribute(flash_kernel,    cudaFuncAttributeMaxDynamicSharedMemorySize, SMEM_FLASH);

    // 1. RMSNorm (both branches) -> hi/lo
    rmsnorm2_kernel<<<ROWS, 256>>>(x, gq, gkv);

    // 2. weight transpose + split
    wtrans_kernel<<<dim3(DD / 32, DD / 32), dim3(32, 8)>>>(Wq, wq_h, wq_l, DD, DD);
    wtrans_kernel<<<dim3(2 * DD / 32, DD / 32), dim3(32, 8)>>>(Wkv, wkv_h, wkv_l, DD, 2 * DD);
    wtrans_kernel<<<dim3(DD / 32, DD / 32), dim3(32, 8)>>>(Wo, wo_h, wo_l, DD, DD);

    // 3. Q projection
    mma_gemm<true><<<dim3(16, 32, 1), 256, SMEM_DYN>>>(
        xq_h, xq_l, wq_h, wq_l, bq, qlin, DD, DD, 0, 0, 0, 1.0f);

    // 4. KV projection
    mma_gemm<true><<<dim3(32, 32, 1), 256, SMEM_DYN>>>(
        xkv_h, xkv_l, wkv_h, wkv_l, bkv, kvlin, DD, 2 * DD, 0, 0, 0, 1.0f);

    // 5. per-head RMSNorm + v transpose
    head_rms_kernel<<<BB * HH * TT, HD>>>(gh);
    vtrans_kernel<<<dim3(TT / 32, HD / 32, BB * HH), dim3(32, 8)>>>();

    // 6. fused flash attention -> d_wvt hi/lo
    flash_kernel<<<dim3(TT / 128, BB * HH), 256, SMEM_FLASH>>>();

    // 7. out = wvt @ Wo^T + bo
    mma_gemm<true><<<dim3(16, 32, 1), 256, SMEM_DYN>>>(
        wvt_h, wvt_l, wo_h, wo_l, bo, out, DD, DD, 0, 0, 0, 1.0f);
}